// round 1
// baseline (speedup 1.0000x reference)
#include <cuda_runtime.h>
#include <cstdint>
#include <cstddef>

#define NB 8192
#define ND 128

#define TI 64
#define TJ 64
#define KC 32
#define APAD 132   // 64x132 floats, rows 528B (16B aligned), conflict-friendly
#define BPAD 36    // 64x36 floats, rows 144B (16B aligned), 2-way conflict on LDS.128

__device__ float        g_S[(size_t)NB * NB];   // 256 MB scratch for similarities
__device__ unsigned     g_minpos[NB];           // monotone-encoded float
__device__ unsigned     g_maxneg[NB];           // monotone-encoded float
__device__ int          g_y[NB];
__device__ float        g_row[NB];
__device__ int          g_valid[NB];
__device__ int          g_is64;

// ---- monotone float<->uint encoding so atomicMin/Max work across signs ----
__device__ __forceinline__ unsigned fenc(float f) {
    unsigned u = __float_as_uint(f);
    return (u & 0x80000000u) ? ~u : (u | 0x80000000u);
}
__device__ __forceinline__ float fdec(unsigned u) {
    return __uint_as_float((u & 0x80000000u) ? (u ^ 0x80000000u) : ~u);
}

// ---- packed fp32x2 FMA (doubles fp32 FMA throughput on sm_103a) ----
__device__ __forceinline__ void ffma2(unsigned long long& c,
                                      unsigned long long a,
                                      unsigned long long b) {
    asm("fma.rn.f32x2 %0, %1, %2, %3;" : "=l"(c) : "l"(a), "l"(b), "l"(c));
}

// ============================================================================
// Kernel 0a: detect whether y is int64 or int32.
// Labels are in [0, 512). If int64, every odd 32-bit word (high half) is 0.
// If int32, the odd words are labels y[1], y[3], ... — all-zero with
// probability (1/512)^2048 ~ 0. Reads only the first 16 KB (safe either way).
// ============================================================================
__global__ void detect_kernel(const unsigned* __restrict__ yraw) {
    __shared__ unsigned red[256];
    unsigned acc = 0;
    for (int t = threadIdx.x; t < 2048; t += 256) acc |= yraw[2 * t + 1];
    red[threadIdx.x] = acc;
    __syncthreads();
    for (int s = 128; s; s >>= 1) {
        if (threadIdx.x < s) red[threadIdx.x] |= red[threadIdx.x + s];
        __syncthreads();
    }
    if (threadIdx.x == 0) g_is64 = (red[0] == 0) ? 1 : 0;
}

// ============================================================================
// Kernel 0b: convert labels to int32, init min/max accumulators.
// ============================================================================
__global__ void init_kernel(const void* __restrict__ yraw) {
    int i = blockIdx.x * blockDim.x + threadIdx.x;
    if (i < NB) {
        int yv = g_is64 ? (int)((const long long*)yraw)[i]
                        : ((const int*)yraw)[i];
        g_y[i] = yv;
        g_minpos[i] = fenc(__int_as_float(0x7f800000));  // +inf
        g_maxneg[i] = fenc(__int_as_float(0xff800000));  // -inf
    }
}

// ============================================================================
// Kernel 1: fused S = x @ x^T, store S, accumulate row-wise min_pos / max_neg.
// Block: 256 threads = 16x16; each thread computes a 4x4 microtile with
// strided row/col mapping (i = ty+16m, j = tx+16n). Accumulators are f32x2
// pairs holding (even-k, odd-k) partial sums, combined in the epilogue.
// Grid: (128 i-tiles, 4 j-chunks); min/max merged across chunks via atomics
// on monotone-encoded uints (order-independent -> deterministic).
// ============================================================================
__global__ void __launch_bounds__(256) pass1_kernel(const float* __restrict__ x) {
    __shared__ float As[TI][APAD];
    __shared__ float Bs[TJ][BPAD];
    __shared__ int yis[TI];
    __shared__ int yjs[TJ];

    const int tid = threadIdx.x;
    const int tx = tid & 15;
    const int ty = tid >> 4;
    const int ib = blockIdx.x * TI;
    const int jc = blockIdx.y * (NB / 4);

    // Load A tile (full K) once per block
    for (int idx = tid; idx < TI * (ND / 4); idx += 256) {
        int r = idx >> 5, c4 = idx & 31;
        float4 v = ((const float4*)x)[(size_t)(ib + r) * (ND / 4) + c4];
        *(float4*)&As[r][c4 * 4] = v;
    }
    if (tid < TI) yis[tid] = g_y[ib + tid];

    float mp[4], mn[4];
#pragma unroll
    for (int m = 0; m < 4; m++) {
        mp[m] = __int_as_float(0x7f800000);
        mn[m] = __int_as_float(0xff800000);
    }

    for (int jt = 0; jt < NB / 4; jt += TJ) {
        const int jb = jc + jt;
        __syncthreads();  // previous epilogue done before yjs/Bs overwrite
        if (tid < TJ) yjs[tid] = g_y[jb + tid];

        unsigned long long c2[4][4];
#pragma unroll
        for (int m = 0; m < 4; m++)
#pragma unroll
            for (int n = 0; n < 4; n++) c2[m][n] = 0ull;

        for (int kc = 0; kc < ND; kc += KC) {
            // load B chunk: 64 rows x 32 k
            for (int idx = tid; idx < TJ * (KC / 4); idx += 256) {
                int r = idx >> 3, c4 = idx & 7;
                float4 v = ((const float4*)x)[(size_t)(jb + r) * (ND / 4) + (kc >> 2) + c4];
                *(float4*)&Bs[r][c4 * 4] = v;
            }
            __syncthreads();

#pragma unroll
            for (int k = 0; k < KC; k += 4) {
                ulonglong2 a2[4], b2[4];
#pragma unroll
                for (int m = 0; m < 4; m++)
                    a2[m] = *(const ulonglong2*)&As[ty + 16 * m][kc + k];
#pragma unroll
                for (int n = 0; n < 4; n++)
                    b2[n] = *(const ulonglong2*)&Bs[tx + 16 * n][k];
#pragma unroll
                for (int m = 0; m < 4; m++)
#pragma unroll
                    for (int n = 0; n < 4; n++) {
                        ffma2(c2[m][n], a2[m].x, b2[n].x);
                        ffma2(c2[m][n], a2[m].y, b2[n].y);
                    }
            }
            __syncthreads();
        }

        // Epilogue: combine pair-partials, store S, update min/max
#pragma unroll
        for (int m = 0; m < 4; m++) {
            const int ii = ib + ty + 16 * m;
            const int yi = yis[ty + 16 * m];
#pragma unroll
            for (int n = 0; n < 4; n++) {
                const int jj = jb + tx + 16 * n;
                unsigned long long cc = c2[m][n];
                float s = __uint_as_float((unsigned)cc) +
                          __uint_as_float((unsigned)(cc >> 32));
                g_S[(size_t)ii * NB + jj] = s;
                const int yj = yjs[tx + 16 * n];
                if (yi == yj) {
                    if (jj != ii) mp[m] = fminf(mp[m], s);
                } else {
                    mn[m] = fmaxf(mn[m], s);
                }
            }
        }
    }

    // Reduce min/max across the 16 tx lanes sharing each row, then atomics.
#pragma unroll
    for (int m = 0; m < 4; m++) {
        float a = mp[m], b = mn[m];
#pragma unroll
        for (int off = 8; off; off >>= 1) {
            a = fminf(a, __shfl_down_sync(0xffffffffu, a, off, 16));
            b = fmaxf(b, __shfl_down_sync(0xffffffffu, b, off, 16));
        }
        if (tx == 0) {
            atomicMin(&g_minpos[ib + ty + 16 * m], fenc(a));
            atomicMax(&g_maxneg[ib + ty + 16 * m], fenc(b));
        }
    }
}

// ============================================================================
// Kernel 2: per-row mining + exp sums. One block per row, streams S[i,:].
// Fixed-order tree reduction -> deterministic.
// ============================================================================
__global__ void __launch_bounds__(256) pass2_kernel() {
    const int i = blockIdx.x;
    const float minp = fdec(g_minpos[i]);
    const float maxn = fdec(g_maxneg[i]);
    const int yi = g_y[i];

    float psum = 0.f, nsum = 0.f;
    int flags = 0;  // bit0 = any pos_keep, bit1 = any neg_keep

    const float4* Srow = (const float4*)(g_S + (size_t)i * NB);
    const int4* y4 = (const int4*)g_y;

    for (int c = threadIdx.x; c < NB / 4; c += 256) {
        float4 s4 = Srow[c];
        int4 yv = y4[c];
        float sv[4] = {s4.x, s4.y, s4.z, s4.w};
        int yy[4] = {yv.x, yv.y, yv.z, yv.w};
        const int j0 = c * 4;
#pragma unroll
        for (int e = 0; e < 4; e++) {
            float s = sv[e];
            int j = j0 + e;
            if (yy[e] != yi) {                    // negative
                if (s + 0.1f > minp) {            // neg_keep
                    flags |= 2;
                    nsum += __expf(50.0f * (s - 1.0f));
                }
            } else if (j != i) {                  // positive (excl. diag)
                if (s - 0.1f < maxn) {            // pos_keep
                    flags |= 1;
                    psum += __expf(-2.0f * (s - 1.0f));
                }
            }
        }
    }

    __shared__ float sp[256];
    __shared__ float sn[256];
    __shared__ int fl[256];
    sp[threadIdx.x] = psum;
    sn[threadIdx.x] = nsum;
    fl[threadIdx.x] = flags;
    __syncthreads();
    for (int s = 128; s; s >>= 1) {
        if (threadIdx.x < s) {
            sp[threadIdx.x] += sp[threadIdx.x + s];
            sn[threadIdx.x] += sn[threadIdx.x + s];
            fl[threadIdx.x] |= fl[threadIdx.x + s];
        }
        __syncthreads();
    }
    if (threadIdx.x == 0) {
        int valid = (fl[0] == 3) ? 1 : 0;
        float pr = 0.5f * log1pf(sp[0]) + 0.02f * log1pf(sn[0]);
        g_row[i] = valid ? pr : 0.f;
        g_valid[i] = valid;
    }
}

// ============================================================================
// Kernel 3: final deterministic reduction over rows.
// ============================================================================
__global__ void __launch_bounds__(256) finalize_kernel(float* __restrict__ out) {
    __shared__ float ssum[256];
    __shared__ int scnt[256];
    float s = 0.f;
    int c = 0;
    for (int i = threadIdx.x; i < NB; i += 256) {
        s += g_row[i];
        c += g_valid[i];
    }
    ssum[threadIdx.x] = s;
    scnt[threadIdx.x] = c;
    __syncthreads();
    for (int k = 128; k; k >>= 1) {
        if (threadIdx.x < k) {
            ssum[threadIdx.x] += ssum[threadIdx.x + k];
            scnt[threadIdx.x] += scnt[threadIdx.x + k];
        }
        __syncthreads();
    }
    if (threadIdx.x == 0) {
        int n = scnt[0];
        out[0] = (n > 0) ? (ssum[0] / (float)n) : 0.f;
    }
}

extern "C" void kernel_launch(void* const* d_in, const int* in_sizes, int n_in,
                              void* d_out, int out_size) {
    const float* x = (const float*)d_in[0];
    const void* y = d_in[1];

    detect_kernel<<<1, 256>>>((const unsigned*)y);
    init_kernel<<<NB / 256, 256>>>(y);

    dim3 g1(NB / TI, 4);
    pass1_kernel<<<g1, 256>>>(x);

    pass2_kernel<<<NB, 256>>>();
    finalize_kernel<<<1, 256>>>((float*)d_out);
}

// round 3
// speedup vs baseline: 1.2156x; 1.2156x over previous
#include <cuda_runtime.h>
#include <cuda_bf16.h>
#include <cstdint>
#include <cstddef>

#define NB 8192
#define ND 128
#define TILE 128
#define NTILE (NB / TILE)       // 64
#define NSTRIP 2
#define NJT (NTILE / NSTRIP)    // 32 j-tiles per CTA

#define KPB 272                 // row pitch in bytes (136 halves): conflict-free ldmatrix
#define ATS 34816               // one 128x128 bf16 tile with pitch 272
#define SM_YIS 0
#define SM_YJS 512              // 2 x 512B (double-buffered with B)
#define SM_A   2048             // hi at +0, lo at +ATS
#define SM_B   (SM_A + 2 * ATS) // buf stride 2*ATS (hi,lo per buf)
#define SMEM_TOTAL (SM_B + 2 * 2 * ATS)   // 210944 B

__device__ __align__(16) __nv_bfloat16 g_xhi[(size_t)NB * ND];
__device__ __align__(16) __nv_bfloat16 g_xlo[(size_t)NB * ND];
__device__ unsigned g_minpos[NB];
__device__ unsigned g_maxneg[NB];
__device__ int g_y[NB];
__device__ float g_ps[4 * NB];
__device__ float g_ns[4 * NB];
__device__ int   g_fl[4 * NB];
__device__ float g_row[NB];
__device__ int   g_valid[NB];
__device__ int   g_is64;

// ---------------- helpers ----------------
__device__ __forceinline__ uint32_t smem_u32(const void* p) {
    uint32_t a;
    asm("{ .reg .u64 t; cvta.to.shared.u64 t, %1; cvt.u32.u64 %0, t; }" : "=r"(a) : "l"(p));
    return a;
}
__device__ __forceinline__ void ldsm4(uint32_t& r0, uint32_t& r1, uint32_t& r2, uint32_t& r3,
                                      uint32_t addr) {
    asm volatile("ldmatrix.sync.aligned.m8n8.x4.shared.b16 {%0,%1,%2,%3}, [%4];"
                 : "=r"(r0), "=r"(r1), "=r"(r2), "=r"(r3) : "r"(addr));
}
__device__ __forceinline__ void mma16816(float* d, const uint32_t* a, const uint32_t* b) {
    asm volatile("mma.sync.aligned.m16n8k16.row.col.f32.bf16.bf16.f32 "
                 "{%0,%1,%2,%3}, {%4,%5,%6,%7}, {%8,%9}, {%0,%1,%2,%3};"
                 : "+f"(d[0]), "+f"(d[1]), "+f"(d[2]), "+f"(d[3])
                 : "r"(a[0]), "r"(a[1]), "r"(a[2]), "r"(a[3]), "r"(b[0]), "r"(b[1]));
}
__device__ __forceinline__ void cpasync16(uint32_t dst, const void* src) {
    asm volatile("cp.async.cg.shared.global [%0], [%1], 16;" :: "r"(dst), "l"(src));
}
#define CP_COMMIT() asm volatile("cp.async.commit_group;" ::: "memory")
#define CP_WAIT0()  asm volatile("cp.async.wait_group 0;" ::: "memory")

__device__ __forceinline__ unsigned fenc(float f) {
    unsigned u = __float_as_uint(f);
    return (u & 0x80000000u) ? ~u : (u | 0x80000000u);
}
__device__ __forceinline__ float fdec(unsigned u) {
    return __uint_as_float((u & 0x80000000u) ? (u ^ 0x80000000u) : ~u);
}

// ---------------- small kernels ----------------
__global__ void detect_kernel(const unsigned* __restrict__ yraw) {
    __shared__ unsigned red[256];
    unsigned acc = 0;
    for (int t = threadIdx.x; t < 2048; t += 256) acc |= yraw[2 * t + 1];
    red[threadIdx.x] = acc;
    __syncthreads();
    for (int s = 128; s; s >>= 1) {
        if (threadIdx.x < s) red[threadIdx.x] |= red[threadIdx.x + s];
        __syncthreads();
    }
    if (threadIdx.x == 0) g_is64 = (red[0] == 0) ? 1 : 0;
}

__global__ void prep_x_kernel(const float* __restrict__ x) {
    int idx = blockIdx.x * 256 + threadIdx.x;
    float v = x[idx];
    __nv_bfloat16 h = __float2bfloat16(v);
    g_xhi[idx] = h;
    g_xlo[idx] = __float2bfloat16(v - __bfloat162float(h));
}

__global__ void init_y_kernel(const void* __restrict__ yraw) {
    int i = blockIdx.x * 256 + threadIdx.x;
    if (i < NB) {
        g_y[i] = g_is64 ? (int)((const long long*)yraw)[i] : ((const int*)yraw)[i];
        g_minpos[i] = fenc(__int_as_float(0x7f800000));
        g_maxneg[i] = fenc(__int_as_float(0xff800000));
    }
}

// ============================================================================
// Fused GEMM + epilogue. MODE 0 = mining (min_pos/max_neg), MODE 1 = loss.
// 8 warps as 4x2; warp tile 32 rows x 64 cols; mma.sync m16n8k16 bf16.
// S accumulated fully in fp32 regs: hi*hi + hi*lo + lo*hi (identical sequence
// in both modes => bit-identical S => self-consistent thresholds).
// ============================================================================
template <int MODE>
__global__ void __launch_bounds__(256, 1) simgemm_kernel() {
    extern __shared__ char smem[];
    const uint32_t sb = smem_u32(smem);
    const int tid = threadIdx.x;
    const int w = tid >> 5, l = tid & 31;
    const int ib = blockIdx.x * TILE;
    const int j0 = blockIdx.y * NJT;

    const int part = tid >> 7;      // 0: hi, 1: lo
    const int r = tid & 127;
    const __nv_bfloat16* src = part ? g_xlo : g_xhi;

    // --- prefetch B tile 0 (hi+lo) + yjs0 via cp.async ---
    {
        const int jb = j0 * TILE;
        const char* sB = (const char*)(src + (size_t)(jb + r) * ND);
        uint32_t bd = sb + SM_B + part * ATS + r * KPB;
#pragma unroll
        for (int t = 0; t < 16; t++) cpasync16(bd + t * 16, sB + t * 16);
        if (tid < 32) cpasync16(sb + SM_YJS + tid * 16, g_y + jb + tid * 4);
        CP_COMMIT();
    }
    // --- resident A tiles (plain LDG->STS) ---
    {
        const uint4* sA = (const uint4*)(src + (size_t)(ib + r) * ND);
        char* ad = smem + SM_A + part * ATS + r * KPB;
#pragma unroll
        for (int t = 0; t < 16; t++) *(uint4*)(ad + t * 16) = sA[t];
    }
    if (tid < 128) ((int*)(smem + SM_YIS))[tid] = g_y[ib + tid];

    // warp/thread geometry
    const int wr = (w & 3) * 32;        // warp row base
    const int wc = (w >> 2) * 64;       // warp col base
    const int g = l >> 3, lr = l & 7;   // ldmatrix lane decode
    const int q = l >> 2;               // quad row (0..7)
    const int e2 = (l & 3) * 2;         // col pair base

    // per-thread rows: wr + mi*16 + h*8 + q  (mi,h in 0..1) -> idx = mi*2+h
    int rowg[4], yrow[4];
    float mp[4], mn[4], ps[4], ns[4], minp[4], maxn[4];
    int fl[4];

    float acc[2][8][4];

    // ldmatrix base offsets (byte offsets within a tile)
    const uint32_t aoff = (uint32_t)((g & 1) * 8 + lr) * KPB + (uint32_t)(g >> 1) * 16;
    const uint32_t boff = (uint32_t)((g >> 1) * 8 + lr) * KPB + (uint32_t)(g & 1) * 16;
    const uint32_t aHi = sb + SM_A;
    const uint32_t aLo = sb + SM_A + ATS;

    __syncthreads();  // A + yis visible

#pragma unroll
    for (int k4 = 0; k4 < 4; k4++) {
        const int rowi = wr + (k4 >> 1) * 16 + (k4 & 1) * 8 + q;
        rowg[k4] = ib + rowi;
        yrow[k4] = ((const int*)(smem + SM_YIS))[rowi];
        mp[k4] = __int_as_float(0x7f800000);
        mn[k4] = __int_as_float(0xff800000);
        ps[k4] = 0.f; ns[k4] = 0.f; fl[k4] = 0;
        if (MODE == 1) {
            minp[k4] = fdec(g_minpos[rowg[k4]]);
            maxn[k4] = fdec(g_maxneg[rowg[k4]]);
        }
    }

    for (int jt = 0; jt < NJT; jt++) {
        const int buf = jt & 1;
        CP_WAIT0();
        __syncthreads();  // B[buf] + yjs[buf] ready; everyone done with B[buf^1]

        // prefetch next B tile into the other buffer (overlaps compute)
        if (jt + 1 < NJT) {
            const int jb = (j0 + jt + 1) * TILE;
            const char* sB = (const char*)(src + (size_t)(jb + r) * ND);
            uint32_t bd = sb + SM_B + (1 - buf) * 2 * ATS + part * ATS + r * KPB;
#pragma unroll
            for (int t = 0; t < 16; t++) cpasync16(bd + t * 16, sB + t * 16);
            if (tid < 32)
                cpasync16(sb + SM_YJS + (1 - buf) * 512 + tid * 16, g_y + jb + tid * 4);
            CP_COMMIT();
        }

#pragma unroll
        for (int mi = 0; mi < 2; mi++)
#pragma unroll
            for (int ni = 0; ni < 8; ni++)
#pragma unroll
                for (int d = 0; d < 4; d++) acc[mi][ni][d] = 0.f;

        const uint32_t bHi = sb + SM_B + buf * 2 * ATS;
        const uint32_t bLo = bHi + ATS;

#pragma unroll
        for (int kc = 0; kc < 8; kc++) {
            const uint32_t ka = (uint32_t)kc * 32;
            uint32_t ah[2][4], al[2][4], bh[8][2], bl[8][2];
#pragma unroll
            for (int mi = 0; mi < 2; mi++) {
                uint32_t o = (uint32_t)(wr + mi * 16) * KPB + aoff + ka;
                ldsm4(ah[mi][0], ah[mi][1], ah[mi][2], ah[mi][3], aHi + o);
                ldsm4(al[mi][0], al[mi][1], al[mi][2], al[mi][3], aLo + o);
            }
#pragma unroll
            for (int nq = 0; nq < 4; nq++) {
                uint32_t o = (uint32_t)(wc + nq * 16) * KPB + boff + ka;
                ldsm4(bh[nq * 2][0], bh[nq * 2][1], bh[nq * 2 + 1][0], bh[nq * 2 + 1][1], bHi + o);
                ldsm4(bl[nq * 2][0], bl[nq * 2][1], bl[nq * 2 + 1][0], bl[nq * 2 + 1][1], bLo + o);
            }
#pragma unroll
            for (int mi = 0; mi < 2; mi++)
#pragma unroll
                for (int ni = 0; ni < 8; ni++) {
                    mma16816(acc[mi][ni], ah[mi], bh[ni]);
                    mma16816(acc[mi][ni], ah[mi], bl[ni]);
                    mma16816(acc[mi][ni], al[mi], bh[ni]);
                }
        }

        // ---- epilogue on registers ----
        const int jb = (j0 + jt) * TILE;
        const int* yjs = (const int*)(smem + SM_YJS + buf * 512);
#pragma unroll
        for (int mi = 0; mi < 2; mi++)
#pragma unroll
            for (int ni = 0; ni < 8; ni++)
#pragma unroll
                for (int h = 0; h < 2; h++) {
                    const int ridx = mi * 2 + h;
#pragma unroll
                    for (int e = 0; e < 2; e++) {
                        const float s = acc[mi][ni][h * 2 + e];
                        const int col = wc + ni * 8 + e2 + e;
                        const int jj = jb + col;
                        const int yj = yjs[col];
                        if (MODE == 0) {
                            if (yj == yrow[ridx]) {
                                if (jj != rowg[ridx]) mp[ridx] = fminf(mp[ridx], s);
                            } else {
                                mn[ridx] = fmaxf(mn[ridx], s);
                            }
                        } else {
                            if (yj != yrow[ridx]) {
                                if (s + 0.1f > minp[ridx]) {
                                    fl[ridx] |= 2;
                                    ns[ridx] += __expf(50.0f * (s - 1.0f));
                                }
                            } else if (jj != rowg[ridx]) {
                                if (s - 0.1f < maxn[ridx]) {
                                    fl[ridx] |= 1;
                                    ps[ridx] += __expf(-2.0f * (s - 1.0f));
                                }
                            }
                        }
                    }
                }
        __syncthreads();  // all warps done with B[buf] before next overwrite-issue
    }

    // ---- cross-lane reduction (4 lanes share each row) + writeout ----
#pragma unroll
    for (int k4 = 0; k4 < 4; k4++) {
        if (MODE == 0) {
            float a = mp[k4], b = mn[k4];
            a = fminf(a, __shfl_xor_sync(0xffffffffu, a, 1));
            a = fminf(a, __shfl_xor_sync(0xffffffffu, a, 2));
            b = fmaxf(b, __shfl_xor_sync(0xffffffffu, b, 1));
            b = fmaxf(b, __shfl_xor_sync(0xffffffffu, b, 2));
            if ((l & 3) == 0) {
                atomicMin(&g_minpos[rowg[k4]], fenc(a));
                atomicMax(&g_maxneg[rowg[k4]], fenc(b));
            }
        } else {
            float a = ps[k4], b = ns[k4];
            int f = fl[k4];
            a += __shfl_xor_sync(0xffffffffu, a, 1);
            a += __shfl_xor_sync(0xffffffffu, a, 2);
            b += __shfl_xor_sync(0xffffffffu, b, 1);
            b += __shfl_xor_sync(0xffffffffu, b, 2);
            f |= __shfl_xor_sync(0xffffffffu, f, 1);
            f |= __shfl_xor_sync(0xffffffffu, f, 2);
            if ((l & 3) == 0) {
                const int slot = blockIdx.y * 2 + (w >> 2);
                g_ps[slot * NB + rowg[k4]] = a;
                g_ns[slot * NB + rowg[k4]] = b;
                g_fl[slot * NB + rowg[k4]] = f;
            }
        }
    }
}

// ---------------- finalize ----------------
__global__ void rowfinal_kernel() {
    int i = blockIdx.x * 256 + threadIdx.x;
    float ps = 0.f, ns = 0.f;
    int fl = 0;
#pragma unroll
    for (int s = 0; s < 4; s++) {
        ps += g_ps[s * NB + i];
        ns += g_ns[s * NB + i];
        fl |= g_fl[s * NB + i];
    }
    int valid = (fl == 3) ? 1 : 0;
    g_row[i] = valid ? (0.5f * log1pf(ps) + 0.02f * log1pf(ns)) : 0.f;
    g_valid[i] = valid;
}

__global__ void __launch_bounds__(256) finalize_kernel(float* __restrict__ out) {
    __shared__ float ssum[256];
    __shared__ int scnt[256];
    float s = 0.f;
    int c = 0;
    for (int i = threadIdx.x; i < NB; i += 256) {
        s += g_row[i];
        c += g_valid[i];
    }
    ssum[threadIdx.x] = s;
    scnt[threadIdx.x] = c;
    __syncthreads();
    for (int k = 128; k; k >>= 1) {
        if (threadIdx.x < k) {
            ssum[threadIdx.x] += ssum[threadIdx.x + k];
            scnt[threadIdx.x] += scnt[threadIdx.x + k];
        }
        __syncthreads();
    }
    if (threadIdx.x == 0) {
        int n = scnt[0];
        out[0] = (n > 0) ? (ssum[0] / (float)n) : 0.f;
    }
}

extern "C" void kernel_launch(void* const* d_in, const int* in_sizes, int n_in,
                              void* d_out, int out_size) {
    const float* x = (const float*)d_in[0];
    const void* y = d_in[1];

    cudaFuncSetAttribute(simgemm_kernel<0>, cudaFuncAttributeMaxDynamicSharedMemorySize, SMEM_TOTAL);
    cudaFuncSetAttribute(simgemm_kernel<1>, cudaFuncAttributeMaxDynamicSharedMemorySize, SMEM_TOTAL);

    detect_kernel<<<1, 256>>>((const unsigned*)y);
    prep_x_kernel<<<NB * ND / 256, 256>>>(x);
    init_y_kernel<<<NB / 256, 256>>>(y);

    dim3 grid(NTILE, NSTRIP);
    simgemm_kernel<0><<<grid, 256, SMEM_TOTAL>>>();
    simgemm_kernel<1><<<grid, 256, SMEM_TOTAL>>>();

    rowfinal_kernel<<<NB / 256, 256>>>();
    finalize_kernel<<<1, 256>>>((float*)d_out);
}

// round 5
// speedup vs baseline: 2.2128x; 1.8203x over previous
#include <cuda_runtime.h>
#include <cuda_bf16.h>
#include <cstdint>
#include <cstddef>

#define NB 8192
#define ND 128
#define TILE 128
#define NTILE (NB / TILE)       // 64
#define NSTRIP 2
#define NJT (NTILE / NSTRIP)    // 32 j-tiles per CTA

#define KPB 272                 // row pitch in bytes (136 halves): conflict-free ldmatrix
#define ATS 34816               // one 128x128 bf16 tile with pitch 272
#define SM_YIS 0
#define SM_YJS 512              // 2 x 512B (double-buffered with B)
#define SM_A   2048             // hi at +0, lo at +ATS
#define SM_B   (SM_A + 2 * ATS) // buf stride 2*ATS (hi,lo per buf)
#define SMEM_TOTAL (SM_B + 2 * 2 * ATS)   // 210944 B

__device__ __align__(16) float g_S[(size_t)NB * NB];   // 256 MB similarity scratch
__device__ __align__(16) __nv_bfloat16 g_xhi[(size_t)NB * ND];
__device__ __align__(16) __nv_bfloat16 g_xlo[(size_t)NB * ND];
__device__ unsigned g_minpos[NB];
__device__ unsigned g_maxneg[NB];
__device__ int g_y[NB];
__device__ float g_row[NB];
__device__ int   g_valid[NB];
__device__ int   g_is64;

// ---------------- helpers ----------------
__device__ __forceinline__ uint32_t smem_u32(const void* p) {
    uint32_t a;
    asm("{ .reg .u64 t; cvta.to.shared.u64 t, %1; cvt.u32.u64 %0, t; }" : "=r"(a) : "l"(p));
    return a;
}
__device__ __forceinline__ void ldsm4(uint32_t& r0, uint32_t& r1, uint32_t& r2, uint32_t& r3,
                                      uint32_t addr) {
    asm volatile("ldmatrix.sync.aligned.m8n8.x4.shared.b16 {%0,%1,%2,%3}, [%4];"
                 : "=r"(r0), "=r"(r1), "=r"(r2), "=r"(r3) : "r"(addr));
}
__device__ __forceinline__ void mma16816(float* d, const uint32_t* a, const uint32_t* b) {
    asm volatile("mma.sync.aligned.m16n8k16.row.col.f32.bf16.bf16.f32 "
                 "{%0,%1,%2,%3}, {%4,%5,%6,%7}, {%8,%9}, {%0,%1,%2,%3};"
                 : "+f"(d[0]), "+f"(d[1]), "+f"(d[2]), "+f"(d[3])
                 : "r"(a[0]), "r"(a[1]), "r"(a[2]), "r"(a[3]), "r"(b[0]), "r"(b[1]));
}
__device__ __forceinline__ void cpasync16(uint32_t dst, const void* src) {
    asm volatile("cp.async.cg.shared.global [%0], [%1], 16;" :: "r"(dst), "l"(src));
}
#define CP_COMMIT() asm volatile("cp.async.commit_group;" ::: "memory")
#define CP_WAIT0()  asm volatile("cp.async.wait_group 0;" ::: "memory")

// streaming (evict-first) store: S is written once, read once much later
__device__ __forceinline__ void stg_cs_f2(float* p, float a, float b) {
    asm volatile("st.global.cs.v2.f32 [%0], {%1, %2};" :: "l"(p), "f"(a), "f"(b) : "memory");
}

__device__ __forceinline__ unsigned fenc(float f) {
    unsigned u = __float_as_uint(f);
    return (u & 0x80000000u) ? ~u : (u | 0x80000000u);
}
__device__ __forceinline__ float fdec(unsigned u) {
    return __uint_as_float((u & 0x80000000u) ? (u ^ 0x80000000u) : ~u);
}

// ---------------- small kernels ----------------
__global__ void detect_kernel(const unsigned* __restrict__ yraw) {
    __shared__ unsigned red[256];
    unsigned acc = 0;
    for (int t = threadIdx.x; t < 2048; t += 256) acc |= yraw[2 * t + 1];
    red[threadIdx.x] = acc;
    __syncthreads();
    for (int s = 128; s; s >>= 1) {
        if (threadIdx.x < s) red[threadIdx.x] |= red[threadIdx.x + s];
        __syncthreads();
    }
    if (threadIdx.x == 0) g_is64 = (red[0] == 0) ? 1 : 0;
}

__global__ void prep_x_kernel(const float* __restrict__ x) {
    int idx = blockIdx.x * 256 + threadIdx.x;
    float v = x[idx];
    __nv_bfloat16 h = __float2bfloat16(v);
    g_xhi[idx] = h;
    g_xlo[idx] = __float2bfloat16(v - __bfloat162float(h));
}

__global__ void init_y_kernel(const void* __restrict__ yraw) {
    int i = blockIdx.x * 256 + threadIdx.x;
    if (i < NB) {
        g_y[i] = g_is64 ? (int)((const long long*)yraw)[i] : ((const int*)yraw)[i];
        g_minpos[i] = fenc(__int_as_float(0x7f800000));
        g_maxneg[i] = fenc(__int_as_float(0xff800000));
    }
}

// ============================================================================
// Pass 1: GEMM (hi*hi + hi*lo + lo*hi, fp32 accum) + store S + mining epilogue.
// 8 warps as 4x2; warp tile 32 rows x 64 cols; mma.sync m16n8k16 bf16.
// Tensor-bound at legacy HMMA rate; the S store rides the idle DRAM pipe.
// ============================================================================
__global__ void __launch_bounds__(256, 1) pass1_kernel() {
    extern __shared__ char smem[];
    const uint32_t sb = smem_u32(smem);
    const int tid = threadIdx.x;
    const int w = tid >> 5, l = tid & 31;
    const int ib = blockIdx.x * TILE;
    const int j0 = blockIdx.y * NJT;

    const int part = tid >> 7;      // 0: hi, 1: lo
    const int r = tid & 127;
    const __nv_bfloat16* src = part ? g_xlo : g_xhi;

    // --- prefetch B tile 0 (hi+lo) + yjs0 via cp.async ---
    {
        const int jb = j0 * TILE;
        const char* sB = (const char*)(src + (size_t)(jb + r) * ND);
        uint32_t bd = sb + SM_B + part * ATS + r * KPB;
#pragma unroll
        for (int t = 0; t < 16; t++) cpasync16(bd + t * 16, sB + t * 16);
        if (tid < 32) cpasync16(sb + SM_YJS + tid * 16, g_y + jb + tid * 4);
        CP_COMMIT();
    }
    // --- resident A tiles ---
    {
        const uint4* sA = (const uint4*)(src + (size_t)(ib + r) * ND);
        char* ad = smem + SM_A + part * ATS + r * KPB;
#pragma unroll
        for (int t = 0; t < 16; t++) *(uint4*)(ad + t * 16) = sA[t];
    }
    if (tid < 128) ((int*)(smem + SM_YIS))[tid] = g_y[ib + tid];

    // warp/thread geometry
    const int wr = (w & 3) * 32;        // warp row base
    const int wc = (w >> 2) * 64;       // warp col base
    const int g = l >> 3, lr = l & 7;   // ldmatrix lane decode
    const int q = l >> 2;               // quad row (0..7)
    const int e2 = (l & 3) * 2;         // col pair base

    int rowg[4], yrow[4];
    float mp[4], mn[4];
    float acc[2][8][4];

    const uint32_t aoff = (uint32_t)((g & 1) * 8 + lr) * KPB + (uint32_t)(g >> 1) * 16;
    const uint32_t boff = (uint32_t)((g >> 1) * 8 + lr) * KPB + (uint32_t)(g & 1) * 16;
    const uint32_t aHi = sb + SM_A;
    const uint32_t aLo = sb + SM_A + ATS;

    __syncthreads();  // A + yis visible

#pragma unroll
    for (int k4 = 0; k4 < 4; k4++) {
        const int rowi = wr + (k4 >> 1) * 16 + (k4 & 1) * 8 + q;
        rowg[k4] = ib + rowi;
        yrow[k4] = ((const int*)(smem + SM_YIS))[rowi];
        mp[k4] = __int_as_float(0x7f800000);
        mn[k4] = __int_as_float(0xff800000);
    }

    for (int jt = 0; jt < NJT; jt++) {
        const int buf = jt & 1;
        CP_WAIT0();
        __syncthreads();  // B[buf] + yjs[buf] ready; everyone done with B[buf^1]

        if (jt + 1 < NJT) {
            const int jb = (j0 + jt + 1) * TILE;
            const char* sB = (const char*)(src + (size_t)(jb + r) * ND);
            uint32_t bd = sb + SM_B + (1 - buf) * 2 * ATS + part * ATS + r * KPB;
#pragma unroll
            for (int t = 0; t < 16; t++) cpasync16(bd + t * 16, sB + t * 16);
            if (tid < 32)
                cpasync16(sb + SM_YJS + (1 - buf) * 512 + tid * 16, g_y + jb + tid * 4);
            CP_COMMIT();
        }

#pragma unroll
        for (int mi = 0; mi < 2; mi++)
#pragma unroll
            for (int ni = 0; ni < 8; ni++)
#pragma unroll
                for (int d = 0; d < 4; d++) acc[mi][ni][d] = 0.f;

        const uint32_t bHi = sb + SM_B + buf * 2 * ATS;
        const uint32_t bLo = bHi + ATS;

#pragma unroll
        for (int kc = 0; kc < 8; kc++) {
            const uint32_t ka = (uint32_t)kc * 32;
            uint32_t ah[2][4], al[2][4], bh[8][2], bl[8][2];
#pragma unroll
            for (int mi = 0; mi < 2; mi++) {
                uint32_t o = (uint32_t)(wr + mi * 16) * KPB + aoff + ka;
                ldsm4(ah[mi][0], ah[mi][1], ah[mi][2], ah[mi][3], aHi + o);
                ldsm4(al[mi][0], al[mi][1], al[mi][2], al[mi][3], aLo + o);
            }
#pragma unroll
            for (int nq = 0; nq < 4; nq++) {
                uint32_t o = (uint32_t)(wc + nq * 16) * KPB + boff + ka;
                ldsm4(bh[nq * 2][0], bh[nq * 2][1], bh[nq * 2 + 1][0], bh[nq * 2 + 1][1], bHi + o);
                ldsm4(bl[nq * 2][0], bl[nq * 2][1], bl[nq * 2 + 1][0], bl[nq * 2 + 1][1], bLo + o);
            }
#pragma unroll
            for (int mi = 0; mi < 2; mi++)
#pragma unroll
                for (int ni = 0; ni < 8; ni++) {
                    mma16816(acc[mi][ni], ah[mi], bh[ni]);
                    mma16816(acc[mi][ni], ah[mi], bl[ni]);
                    mma16816(acc[mi][ni], al[mi], bh[ni]);
                }
        }

        // ---- epilogue: store S (streaming) + mining ----
        const int jb = (j0 + jt) * TILE;
        const int* yjs = (const int*)(smem + SM_YJS + buf * 512);
#pragma unroll
        for (int mi = 0; mi < 2; mi++)
#pragma unroll
            for (int h = 0; h < 2; h++) {
                const int ridx = mi * 2 + h;
                float* srow = g_S + (size_t)rowg[ridx] * NB + jb;
#pragma unroll
                for (int ni = 0; ni < 8; ni++) {
                    const float s0 = acc[mi][ni][h * 2 + 0];
                    const float s1 = acc[mi][ni][h * 2 + 1];
                    const int col = wc + ni * 8 + e2;
                    stg_cs_f2(srow + col, s0, s1);
#pragma unroll
                    for (int e = 0; e < 2; e++) {
                        const float s = e ? s1 : s0;
                        const int jj = jb + col + e;
                        const int yj = yjs[col + e];
                        if (yj == yrow[ridx]) {
                            if (jj != rowg[ridx]) mp[ridx] = fminf(mp[ridx], s);
                        } else {
                            mn[ridx] = fmaxf(mn[ridx], s);
                        }
                    }
                }
            }
        __syncthreads();  // all warps done with B[buf] before next overwrite-issue
    }

    // ---- cross-lane reduction (4 lanes share each row) + atomics ----
#pragma unroll
    for (int k4 = 0; k4 < 4; k4++) {
        float a = mp[k4], b = mn[k4];
        a = fminf(a, __shfl_xor_sync(0xffffffffu, a, 1));
        a = fminf(a, __shfl_xor_sync(0xffffffffu, a, 2));
        b = fmaxf(b, __shfl_xor_sync(0xffffffffu, b, 1));
        b = fmaxf(b, __shfl_xor_sync(0xffffffffu, b, 2));
        if ((l & 3) == 0) {
            atomicMin(&g_minpos[rowg[k4]], fenc(a));
            atomicMax(&g_maxneg[rowg[k4]], fenc(b));
        }
    }
}

// ============================================================================
// Pass 2: per-row mining + exp sums (streams stored S). Deterministic.
// ============================================================================
__global__ void __launch_bounds__(256) pass2_kernel() {
    const int i = blockIdx.x;
    const float minp = fdec(g_minpos[i]);
    const float maxn = fdec(g_maxneg[i]);
    const int yi = g_y[i];

    float psum = 0.f, nsum = 0.f;
    int flags = 0;

    const float4* Srow = (const float4*)(g_S + (size_t)i * NB);
    const int4* y4 = (const int4*)g_y;

    for (int c = threadIdx.x; c < NB / 4; c += 256) {
        float4 s4 = __ldcs(Srow + c);   // streaming read: read-once data
        int4 yv = y4[c];
        float sv[4] = {s4.x, s4.y, s4.z, s4.w};
        int yy[4] = {yv.x, yv.y, yv.z, yv.w};
        const int j0 = c * 4;
#pragma unroll
        for (int e = 0; e < 4; e++) {
            float s = sv[e];
            int j = j0 + e;
            if (yy[e] != yi) {
                if (s + 0.1f > minp) {
                    flags |= 2;
                    nsum += __expf(50.0f * (s - 1.0f));
                }
            } else if (j != i) {
                if (s - 0.1f < maxn) {
                    flags |= 1;
                    psum += __expf(-2.0f * (s - 1.0f));
                }
            }
        }
    }

    __shared__ float sp[256];
    __shared__ float sn[256];
    __shared__ int fl[256];
    sp[threadIdx.x] = psum;
    sn[threadIdx.x] = nsum;
    fl[threadIdx.x] = flags;
    __syncthreads();
    for (int s = 128; s; s >>= 1) {
        if (threadIdx.x < s) {
            sp[threadIdx.x] += sp[threadIdx.x + s];
            sn[threadIdx.x] += sn[threadIdx.x + s];
            fl[threadIdx.x] |= fl[threadIdx.x + s];
        }
        __syncthreads();
    }
    if (threadIdx.x == 0) {
        int valid = (fl[0] == 3) ? 1 : 0;
        g_row[i] = valid ? (0.5f * log1pf(sp[0]) + 0.02f * log1pf(sn[0])) : 0.f;
        g_valid[i] = valid;
    }
}

__global__ void __launch_bounds__(256) finalize_kernel(float* __restrict__ out) {
    __shared__ float ssum[256];
    __shared__ int scnt[256];
    float s = 0.f;
    int c = 0;
    for (int i = threadIdx.x; i < NB; i += 256) {
        s += g_row[i];
        c += g_valid[i];
    }
    ssum[threadIdx.x] = s;
    scnt[threadIdx.x] = c;
    __syncthreads();
    for (int k = 128; k; k >>= 1) {
        if (threadIdx.x < k) {
            ssum[threadIdx.x] += ssum[threadIdx.x + k];
            scnt[threadIdx.x] += scnt[threadIdx.x + k];
        }
        __syncthreads();
    }
    if (threadIdx.x == 0) {
        int n = scnt[0];
        out[0] = (n > 0) ? (ssum[0] / (float)n) : 0.f;
    }
}

extern "C" void kernel_launch(void* const* d_in, const int* in_sizes, int n_in,
                              void* d_out, int out_size) {
    const float* x = (const float*)d_in[0];
    const void* y = d_in[1];

    cudaFuncSetAttribute(pass1_kernel, cudaFuncAttributeMaxDynamicSharedMemorySize, SMEM_TOTAL);

    detect_kernel<<<1, 256>>>((const unsigned*)y);
    prep_x_kernel<<<NB * ND / 256, 256>>>(x);
    init_y_kernel<<<NB / 256, 256>>>(y);

    dim3 grid(NTILE, NSTRIP);
    pass1_kernel<<<grid, 256, SMEM_TOTAL>>>();

    pass2_kernel<<<NB, 256>>>();
    finalize_kernel<<<1, 256>>>((float*)d_out);
}

// round 6
// speedup vs baseline: 2.5217x; 1.1396x over previous
#include <cuda_runtime.h>
#include <cuda_bf16.h>
#include <cstdint>
#include <cstddef>

#define NB 8192
#define ND 128
#define TILE 128
#define NTILE (NB / TILE)       // 64
#define NTRI  (NTILE * (NTILE + 1) / 2)   // 2080 triangular tiles

#define KPB 272                 // row pitch in bytes (136 halves): conflict-free ldmatrix
#define ATS 34816               // one 128x128 bf16 tile with pitch 272
#define SM_YIS 0
#define SM_YJS 512
#define SM_A   2048             // hi at +0, lo at +ATS
#define SM_B   (SM_A + 2 * ATS) // B hi/lo; reused as fp32 transpose staging in epilogue
#define SMEM_TOTAL (SM_B + 2 * ATS)       // 141312 B
#define TPIT 132                // staging pitch (floats): bank-conflict-free

__device__ __align__(16) float g_S[(size_t)NB * NB];   // 256 MB similarity scratch
__device__ __align__(16) __nv_bfloat16 g_xhi[(size_t)NB * ND];
__device__ __align__(16) __nv_bfloat16 g_xlo[(size_t)NB * ND];
__device__ unsigned g_minpos[NB];
__device__ unsigned g_maxneg[NB];
__device__ int g_y[NB];
__device__ float g_row[NB];
__device__ int   g_valid[NB];
__device__ int   g_is64;

// ---------------- helpers ----------------
__device__ __forceinline__ uint32_t smem_u32(const void* p) {
    uint32_t a;
    asm("{ .reg .u64 t; cvta.to.shared.u64 t, %1; cvt.u32.u64 %0, t; }" : "=r"(a) : "l"(p));
    return a;
}
__device__ __forceinline__ void ldsm4(uint32_t& r0, uint32_t& r1, uint32_t& r2, uint32_t& r3,
                                      uint32_t addr) {
    asm volatile("ldmatrix.sync.aligned.m8n8.x4.shared.b16 {%0,%1,%2,%3}, [%4];"
                 : "=r"(r0), "=r"(r1), "=r"(r2), "=r"(r3) : "r"(addr));
}
__device__ __forceinline__ void mma16816(float* d, const uint32_t* a, const uint32_t* b) {
    asm volatile("mma.sync.aligned.m16n8k16.row.col.f32.bf16.bf16.f32 "
                 "{%0,%1,%2,%3}, {%4,%5,%6,%7}, {%8,%9}, {%0,%1,%2,%3};"
                 : "+f"(d[0]), "+f"(d[1]), "+f"(d[2]), "+f"(d[3])
                 : "r"(a[0]), "r"(a[1]), "r"(a[2]), "r"(a[3]), "r"(b[0]), "r"(b[1]));
}
__device__ __forceinline__ void cpasync16(uint32_t dst, const void* src) {
    asm volatile("cp.async.cg.shared.global [%0], [%1], 16;" :: "r"(dst), "l"(src));
}
#define CP_COMMIT() asm volatile("cp.async.commit_group;" ::: "memory")
__device__ __forceinline__ void cp_wait(int n) {
    switch (n) {
        case 0: asm volatile("cp.async.wait_group 0;" ::: "memory"); break;
        case 1: asm volatile("cp.async.wait_group 1;" ::: "memory"); break;
        case 2: asm volatile("cp.async.wait_group 2;" ::: "memory"); break;
        case 3: asm volatile("cp.async.wait_group 3;" ::: "memory"); break;
        case 4: asm volatile("cp.async.wait_group 4;" ::: "memory"); break;
        case 5: asm volatile("cp.async.wait_group 5;" ::: "memory"); break;
        case 6: asm volatile("cp.async.wait_group 6;" ::: "memory"); break;
        default: asm volatile("cp.async.wait_group 7;" ::: "memory"); break;
    }
}

// streaming (evict-first) stores: S is written once, read once much later
__device__ __forceinline__ void stg_cs_f2(float* p, float a, float b) {
    asm volatile("st.global.cs.v2.f32 [%0], {%1, %2};" :: "l"(p), "f"(a), "f"(b) : "memory");
}
__device__ __forceinline__ void stg_cs_f4(float* p, float4 v) {
    asm volatile("st.global.cs.v4.f32 [%0], {%1, %2, %3, %4};"
                 :: "l"(p), "f"(v.x), "f"(v.y), "f"(v.z), "f"(v.w) : "memory");
}

__device__ __forceinline__ unsigned fenc(float f) {
    unsigned u = __float_as_uint(f);
    return (u & 0x80000000u) ? ~u : (u | 0x80000000u);
}
__device__ __forceinline__ float fdec(unsigned u) {
    return __uint_as_float((u & 0x80000000u) ? (u ^ 0x80000000u) : ~u);
}

// ---------------- small kernels ----------------
__global__ void detect_kernel(const unsigned* __restrict__ yraw) {
    __shared__ unsigned red[256];
    unsigned acc = 0;
    for (int t = threadIdx.x; t < 2048; t += 256) acc |= yraw[2 * t + 1];
    red[threadIdx.x] = acc;
    __syncthreads();
    for (int s = 128; s; s >>= 1) {
        if (threadIdx.x < s) red[threadIdx.x] |= red[threadIdx.x + s];
        __syncthreads();
    }
    if (threadIdx.x == 0) g_is64 = (red[0] == 0) ? 1 : 0;
}

__global__ void prep_x_kernel(const float* __restrict__ x) {
    int idx = blockIdx.x * 256 + threadIdx.x;
    float v = x[idx];
    __nv_bfloat16 h = __float2bfloat16(v);
    g_xhi[idx] = h;
    g_xlo[idx] = __float2bfloat16(v - __bfloat162float(h));
}

__global__ void init_y_kernel(const void* __restrict__ yraw) {
    int i = blockIdx.x * 256 + threadIdx.x;
    if (i < NB) {
        g_y[i] = g_is64 ? (int)((const long long*)yraw)[i] : ((const int*)yraw)[i];
        g_minpos[i] = fenc(__int_as_float(0x7f800000));
        g_maxneg[i] = fenc(__int_as_float(0xff800000));
    }
}

// ============================================================================
// Pass 1 (triangular): one CTA per tile (it, jt) with jt >= it.
// GEMM hi*hi + hi*lo + lo*hi, fp32 accum; store S block + mirror block;
// mining on both row-side (i rows) and column-side (j rows, via smem
// transpose staged into the dead B buffer).
// ============================================================================
__global__ void __launch_bounds__(256, 1) pass1_kernel() {
    extern __shared__ char smem[];
    const uint32_t sb = smem_u32(smem);
    const int tid = threadIdx.x;
    const int w = tid >> 5, l = tid & 31;

    // --- triangular decode of blockIdx.x -> (it, jt), jt >= it ---
    const int b = blockIdx.x;
    int it = (int)((129.0f - sqrtf(129.0f * 129.0f - 8.0f * (float)b)) * 0.5f);
    if (it > NTILE - 1) it = NTILE - 1;
    if (it < 0) it = 0;
    while (it + 1 <= NTILE - 1 && ((129 * (it + 1) - (it + 1) * (it + 1)) / 2) <= b) it++;
    while (((129 * it - it * it) / 2) > b) it--;
    const int jt = it + (b - (129 * it - it * it) / 2);

    const int ib = it * TILE;
    const int jb = jt * TILE;

    const int part = tid >> 7;      // 0: hi, 1: lo
    const int r = tid & 127;
    const __nv_bfloat16* src = part ? g_xlo : g_xhi;
    const char* srcA = (const char*)(src + (size_t)(ib + r) * ND);
    const char* srcB = (const char*)(src + (size_t)(jb + r) * ND);
    const uint32_t dstA = sb + SM_A + part * ATS + r * KPB;
    const uint32_t dstB = sb + SM_B + part * ATS + r * KPB;

    // 8 commit groups, one per k-chunk (A + B slices together)
#pragma unroll
    for (int kc = 0; kc < 8; kc++) {
        const int o = kc * 32;
        cpasync16(dstA + o, srcA + o);
        cpasync16(dstA + o + 16, srcA + o + 16);
        cpasync16(dstB + o, srcB + o);
        cpasync16(dstB + o + 16, srcB + o + 16);
        CP_COMMIT();
    }
    if (tid < 128) {
        ((int*)(smem + SM_YIS))[tid] = g_y[ib + tid];
        ((int*)(smem + SM_YJS))[tid] = g_y[jb + tid];
    }

    // warp/thread geometry
    const int wr = (w & 3) * 32;        // warp row base
    const int wc = (w >> 2) * 64;       // warp col base
    const int g = l >> 3, lr = l & 7;   // ldmatrix lane decode
    const int q = l >> 2;               // quad row (0..7)
    const int e2 = (l & 3) * 2;         // col pair base

    const uint32_t aoff = (uint32_t)((g & 1) * 8 + lr) * KPB + (uint32_t)(g >> 1) * 16;
    const uint32_t boff = (uint32_t)((g >> 1) * 8 + lr) * KPB + (uint32_t)(g & 1) * 16;
    const uint32_t aHi = sb + SM_A;
    const uint32_t aLo = sb + SM_A + ATS;
    const uint32_t bHi = sb + SM_B;
    const uint32_t bLo = sb + SM_B + ATS;

    float acc[2][8][4];
#pragma unroll
    for (int mi = 0; mi < 2; mi++)
#pragma unroll
        for (int ni = 0; ni < 8; ni++)
#pragma unroll
            for (int d = 0; d < 4; d++) acc[mi][ni][d] = 0.f;

#pragma unroll
    for (int kc = 0; kc < 8; kc++) {
        cp_wait(7 - kc);
        __syncthreads();
        const uint32_t ka = (uint32_t)kc * 32;
        uint32_t ah[2][4], al[2][4], bh[8][2], bl[8][2];
#pragma unroll
        for (int mi = 0; mi < 2; mi++) {
            uint32_t o = (uint32_t)(wr + mi * 16) * KPB + aoff + ka;
            ldsm4(ah[mi][0], ah[mi][1], ah[mi][2], ah[mi][3], aHi + o);
            ldsm4(al[mi][0], al[mi][1], al[mi][2], al[mi][3], aLo + o);
        }
#pragma unroll
        for (int nq = 0; nq < 4; nq++) {
            uint32_t o = (uint32_t)(wc + nq * 16) * KPB + boff + ka;
            ldsm4(bh[nq * 2][0], bh[nq * 2][1], bh[nq * 2 + 1][0], bh[nq * 2 + 1][1], bHi + o);
            ldsm4(bl[nq * 2][0], bl[nq * 2][1], bl[nq * 2 + 1][0], bl[nq * 2 + 1][1], bLo + o);
        }
#pragma unroll
        for (int mi = 0; mi < 2; mi++)
#pragma unroll
            for (int ni = 0; ni < 8; ni++) {
                mma16816(acc[mi][ni], ah[mi], bh[ni]);
                mma16816(acc[mi][ni], ah[mi], bl[ni]);
                mma16816(acc[mi][ni], al[mi], bh[ni]);
            }
    }

    // ---- epilogue (a): direct store of S(it,jt) + row-side mining ----
    int rowg[4], yrow[4];
    float mp[4], mn[4];
#pragma unroll
    for (int k4 = 0; k4 < 4; k4++) {
        const int rowi = wr + (k4 >> 1) * 16 + (k4 & 1) * 8 + q;
        rowg[k4] = ib + rowi;
        yrow[k4] = ((const int*)(smem + SM_YIS))[rowi];
        mp[k4] = __int_as_float(0x7f800000);
        mn[k4] = __int_as_float(0xff800000);
    }
    const int* yjs = (const int*)(smem + SM_YJS);
#pragma unroll
    for (int mi = 0; mi < 2; mi++)
#pragma unroll
        for (int h = 0; h < 2; h++) {
            const int ridx = mi * 2 + h;
            float* srow = g_S + (size_t)rowg[ridx] * NB + jb;
#pragma unroll
            for (int ni = 0; ni < 8; ni++) {
                const float s0 = acc[mi][ni][h * 2 + 0];
                const float s1 = acc[mi][ni][h * 2 + 1];
                const int col = wc + ni * 8 + e2;
                stg_cs_f2(srow + col, s0, s1);
#pragma unroll
                for (int e = 0; e < 2; e++) {
                    const float s = e ? s1 : s0;
                    const int jj = jb + col + e;
                    const int yj = yjs[col + e];
                    if (yj == yrow[ridx]) {
                        if (jj != rowg[ridx]) mp[ridx] = fminf(mp[ridx], s);
                    } else {
                        mn[ridx] = fmaxf(mn[ridx], s);
                    }
                }
            }
        }
#pragma unroll
    for (int k4 = 0; k4 < 4; k4++) {
        float a = mp[k4], bv = mn[k4];
        a = fminf(a, __shfl_xor_sync(0xffffffffu, a, 1));
        a = fminf(a, __shfl_xor_sync(0xffffffffu, a, 2));
        bv = fmaxf(bv, __shfl_xor_sync(0xffffffffu, bv, 1));
        bv = fmaxf(bv, __shfl_xor_sync(0xffffffffu, bv, 2));
        if ((l & 3) == 0) {
            atomicMin(&g_minpos[rowg[k4]], fenc(a));
            atomicMax(&g_maxneg[rowg[k4]], fenc(bv));
        }
    }

    // ---- epilogue (b): mirror block + column-side mining (off-diagonal) ----
    if (it != jt) {
        __syncthreads();  // everyone done reading B smem before staging overwrite
        float* stg = (float*)(smem + SM_B);
#pragma unroll
        for (int mi = 0; mi < 2; mi++)
#pragma unroll
            for (int h = 0; h < 2; h++) {
                const int row = wr + mi * 16 + h * 8 + q;
#pragma unroll
                for (int ni = 0; ni < 8; ni++) {
                    const int col = wc + ni * 8 + e2;
                    stg[(col) * TPIT + row] = acc[mi][ni][h * 2 + 0];
                    stg[(col + 1) * TPIT + row] = acc[mi][ni][h * 2 + 1];
                }
            }
        __syncthreads();
        const int* yis = (const int*)(smem + SM_YIS);
#pragma unroll
        for (int iter = 0; iter < 16; iter++) {
            const int jr = iter * 8 + w;               // staged row = original col
            const int yj = yjs[jr];
            float4 v = *(const float4*)&stg[jr * TPIT + l * 4];
            stg_cs_f4(g_S + (size_t)(jb + jr) * NB + ib + l * 4, v);
            float cmp = __int_as_float(0x7f800000);
            float cmx = __int_as_float(0xff800000);
            const float vv[4] = {v.x, v.y, v.z, v.w};
#pragma unroll
            for (int e = 0; e < 4; e++) {
                const int yi_ = yis[l * 4 + e];
                if (yi_ == yj) cmp = fminf(cmp, vv[e]);  // i != j off-diagonal
                else cmx = fmaxf(cmx, vv[e]);
            }
#pragma unroll
            for (int off = 16; off; off >>= 1) {
                cmp = fminf(cmp, __shfl_xor_sync(0xffffffffu, cmp, off));
                cmx = fmaxf(cmx, __shfl_xor_sync(0xffffffffu, cmx, off));
            }
            if (l == 0) {
                atomicMin(&g_minpos[jb + jr], fenc(cmp));
                atomicMax(&g_maxneg[jb + jr], fenc(cmx));
            }
        }
    }
}

// ============================================================================
// Pass 2: per-row mining + exp sums (streams stored S). Deterministic.
// ============================================================================
__global__ void __launch_bounds__(256) pass2_kernel() {
    const int i = blockIdx.x;
    const float minp = fdec(g_minpos[i]);
    const float maxn = fdec(g_maxneg[i]);
    const int yi = g_y[i];

    float psum = 0.f, nsum = 0.f;
    int flags = 0;

    const float4* Srow = (const float4*)(g_S + (size_t)i * NB);
    const int4* y4 = (const int4*)g_y;

    for (int c = threadIdx.x; c < NB / 4; c += 256) {
        float4 s4 = __ldcs(Srow + c);   // streaming read: read-once data
        int4 yv = y4[c];
        float sv[4] = {s4.x, s4.y, s4.z, s4.w};
        int yy[4] = {yv.x, yv.y, yv.z, yv.w};
        const int j0 = c * 4;
#pragma unroll
        for (int e = 0; e < 4; e++) {
            float s = sv[e];
            int j = j0 + e;
            if (yy[e] != yi) {
                if (s + 0.1f > minp) {
                    flags |= 2;
                    nsum += __expf(50.0f * (s - 1.0f));
                }
            } else if (j != i) {
                if (s - 0.1f < maxn) {
                    flags |= 1;
                    psum += __expf(-2.0f * (s - 1.0f));
                }
            }
        }
    }

    __shared__ float sp[256];
    __shared__ float sn[256];
    __shared__ int fl[256];
    sp[threadIdx.x] = psum;
    sn[threadIdx.x] = nsum;
    fl[threadIdx.x] = flags;
    __syncthreads();
    for (int s = 128; s; s >>= 1) {
        if (threadIdx.x < s) {
            sp[threadIdx.x] += sp[threadIdx.x + s];
            sn[threadIdx.x] += sn[threadIdx.x + s];
            fl[threadIdx.x] |= fl[threadIdx.x + s];
        }
        __syncthreads();
    }
    if (threadIdx.x == 0) {
        int valid = (fl[0] == 3) ? 1 : 0;
        g_row[i] = valid ? (0.5f * log1pf(sp[0]) + 0.02f * log1pf(sn[0])) : 0.f;
        g_valid[i] = valid;
    }
}

__global__ void __launch_bounds__(256) finalize_kernel(float* __restrict__ out) {
    __shared__ float ssum[256];
    __shared__ int scnt[256];
    float s = 0.f;
    int c = 0;
    for (int i = threadIdx.x; i < NB; i += 256) {
        s += g_row[i];
        c += g_valid[i];
    }
    ssum[threadIdx.x] = s;
    scnt[threadIdx.x] = c;
    __syncthreads();
    for (int k = 128; k; k >>= 1) {
        if (threadIdx.x < k) {
            ssum[threadIdx.x] += ssum[threadIdx.x + k];
            scnt[threadIdx.x] += scnt[threadIdx.x + k];
        }
        __syncthreads();
    }
    if (threadIdx.x == 0) {
        int n = scnt[0];
        out[0] = (n > 0) ? (ssum[0] / (float)n) : 0.f;
    }
}

extern "C" void kernel_launch(void* const* d_in, const int* in_sizes, int n_in,
                              void* d_out, int out_size) {
    const float* x = (const float*)d_in[0];
    const void* y = d_in[1];

    cudaFuncSetAttribute(pass1_kernel, cudaFuncAttributeMaxDynamicSharedMemorySize, SMEM_TOTAL);

    detect_kernel<<<1, 256>>>((const unsigned*)y);
    prep_x_kernel<<<NB * ND / 256, 256>>>(x);
    init_y_kernel<<<NB / 256, 256>>>(y);

    pass1_kernel<<<NTRI, 256, SMEM_TOTAL>>>();

    pass2_kernel<<<NB, 256>>>();
    finalize_kernel<<<1, 256>>>((float*)d_out);
}

// round 7
// speedup vs baseline: 2.5537x; 1.0127x over previous
#include <cuda_runtime.h>
#include <cuda_bf16.h>
#include <cstdint>
#include <cstddef>

#define NB 8192
#define ND 128
#define TILE 128
#define NTILE (NB / TILE)       // 64
#define NTRI  (NTILE * (NTILE + 1) / 2)   // 2080 triangular tiles

#define KPB 272                 // row pitch in bytes (136 halves): conflict-free ldmatrix
#define ATS 34816               // one 128x128 bf16 tile with pitch 272
#define SM_YIS 0
#define SM_YJS 512
#define SM_A   2048             // hi at +0, lo at +ATS  (reused: column-mining tables)
#define SM_B   (SM_A + 2 * ATS) // B hi/lo; reused as fp32 transpose staging in epilogue
#define SMEM_TOTAL (SM_B + 2 * ATS)       // 141312 B
#define TPIT 132                // staging pitch (floats): bank-conflict-free
#define CTS 36                  // column-table stride (floats): 16B-aligned, conflict-free

__device__ __align__(16) float g_S[(size_t)NB * NB];   // 256 MB similarity scratch
__device__ __align__(16) __nv_bfloat16 g_xhi[(size_t)NB * ND];
__device__ __align__(16) __nv_bfloat16 g_xlo[(size_t)NB * ND];
__device__ unsigned g_minpos[NB];
__device__ unsigned g_maxneg[NB];
__device__ int g_y[NB];
__device__ float g_row[NB];
__device__ int   g_valid[NB];
__device__ int   g_is64;

// ---------------- helpers ----------------
__device__ __forceinline__ uint32_t smem_u32(const void* p) {
    uint32_t a;
    asm("{ .reg .u64 t; cvta.to.shared.u64 t, %1; cvt.u32.u64 %0, t; }" : "=r"(a) : "l"(p));
    return a;
}
__device__ __forceinline__ void ldsm4(uint32_t& r0, uint32_t& r1, uint32_t& r2, uint32_t& r3,
                                      uint32_t addr) {
    asm volatile("ldmatrix.sync.aligned.m8n8.x4.shared.b16 {%0,%1,%2,%3}, [%4];"
                 : "=r"(r0), "=r"(r1), "=r"(r2), "=r"(r3) : "r"(addr));
}
__device__ __forceinline__ void mma16816(float* d, const uint32_t* a, const uint32_t* b) {
    asm volatile("mma.sync.aligned.m16n8k16.row.col.f32.bf16.bf16.f32 "
                 "{%0,%1,%2,%3}, {%4,%5,%6,%7}, {%8,%9}, {%0,%1,%2,%3};"
                 : "+f"(d[0]), "+f"(d[1]), "+f"(d[2]), "+f"(d[3])
                 : "r"(a[0]), "r"(a[1]), "r"(a[2]), "r"(a[3]), "r"(b[0]), "r"(b[1]));
}
__device__ __forceinline__ void cpasync16(uint32_t dst, const void* src) {
    asm volatile("cp.async.cg.shared.global [%0], [%1], 16;" :: "r"(dst), "l"(src));
}
#define CP_COMMIT() asm volatile("cp.async.commit_group;" ::: "memory")
__device__ __forceinline__ void cp_wait(int n) {
    switch (n) {
        case 0: asm volatile("cp.async.wait_group 0;" ::: "memory"); break;
        case 1: asm volatile("cp.async.wait_group 1;" ::: "memory"); break;
        case 2: asm volatile("cp.async.wait_group 2;" ::: "memory"); break;
        case 3: asm volatile("cp.async.wait_group 3;" ::: "memory"); break;
        case 4: asm volatile("cp.async.wait_group 4;" ::: "memory"); break;
        case 5: asm volatile("cp.async.wait_group 5;" ::: "memory"); break;
        case 6: asm volatile("cp.async.wait_group 6;" ::: "memory"); break;
        default: asm volatile("cp.async.wait_group 7;" ::: "memory"); break;
    }
}

// streaming (evict-first) stores: S is written once, read once much later
__device__ __forceinline__ void stg_cs_f2(float* p, float a, float b) {
    asm volatile("st.global.cs.v2.f32 [%0], {%1, %2};" :: "l"(p), "f"(a), "f"(b) : "memory");
}
__device__ __forceinline__ void stg_cs_f4(float* p, float4 v) {
    asm volatile("st.global.cs.v4.f32 [%0], {%1, %2, %3, %4};"
                 :: "l"(p), "f"(v.x), "f"(v.y), "f"(v.z), "f"(v.w) : "memory");
}

__device__ __forceinline__ unsigned fenc(float f) {
    unsigned u = __float_as_uint(f);
    return (u & 0x80000000u) ? ~u : (u | 0x80000000u);
}
__device__ __forceinline__ float fdec(unsigned u) {
    return __uint_as_float((u & 0x80000000u) ? (u ^ 0x80000000u) : ~u);
}

// ---------------- small kernels ----------------
__global__ void detect_kernel(const unsigned* __restrict__ yraw) {
    __shared__ unsigned red[256];
    unsigned acc = 0;
    for (int t = threadIdx.x; t < 2048; t += 256) acc |= yraw[2 * t + 1];
    red[threadIdx.x] = acc;
    __syncthreads();
    for (int s = 128; s; s >>= 1) {
        if (threadIdx.x < s) red[threadIdx.x] |= red[threadIdx.x + s];
        __syncthreads();
    }
    if (threadIdx.x == 0) g_is64 = (red[0] == 0) ? 1 : 0;
}

__global__ void prep_x_kernel(const float* __restrict__ x) {
    int idx = blockIdx.x * 256 + threadIdx.x;
    float v = x[idx];
    __nv_bfloat16 h = __float2bfloat16(v);
    g_xhi[idx] = h;
    g_xlo[idx] = __float2bfloat16(v - __bfloat162float(h));
}

__global__ void init_y_kernel(const void* __restrict__ yraw) {
    int i = blockIdx.x * 256 + threadIdx.x;
    if (i < NB) {
        g_y[i] = g_is64 ? (int)((const long long*)yraw)[i] : ((const int*)yraw)[i];
        g_minpos[i] = fenc(__int_as_float(0x7f800000));
        g_maxneg[i] = fenc(__int_as_float(0xff800000));
    }
}

// ============================================================================
// Pass 1 (triangular, 512 threads): one CTA per tile (it, jt), jt >= it.
// 16 warps as 4x4 grid of 32x32 warp tiles. GEMM hi*hi + hi*lo + lo*hi in
// fp32 accum; store S block + mirror block; mining on row side (registers +
// shfl) and column side (register partials -> smem tables -> 128-thread
// reduce), transpose staging only for the coalesced mirror store.
// ============================================================================
__global__ void __launch_bounds__(512, 1) pass1_kernel() {
    extern __shared__ char smem[];
    const uint32_t sb = smem_u32(smem);
    const int tid = threadIdx.x;
    const int w = tid >> 5, l = tid & 31;

    // --- triangular decode of blockIdx.x -> (it, jt), jt >= it ---
    const int b = blockIdx.x;
    int it = (int)((129.0f - sqrtf(129.0f * 129.0f - 8.0f * (float)b)) * 0.5f);
    if (it > NTILE - 1) it = NTILE - 1;
    if (it < 0) it = 0;
    while (it + 1 <= NTILE - 1 && ((129 * (it + 1) - (it + 1) * (it + 1)) / 2) <= b) it++;
    while (((129 * it - it * it) / 2) > b) it--;
    const int jt = it + (b - (129 * it - it * it) / 2);

    const int ib = it * TILE;
    const int jb = jt * TILE;

    // --- loads: part = Ahi / Alo / Bhi / Blo, one row-slice per thread ---
    {
        const int part = tid >> 7;      // 0..3
        const int r = tid & 127;
        const __nv_bfloat16* src =
            (part & 1) ? (g_xlo + (size_t)(((part >> 1) ? jb : ib) + r) * ND)
                       : (g_xhi + (size_t)(((part >> 1) ? jb : ib) + r) * ND);
        const char* srow = (const char*)src;
        const uint32_t dst = sb + ((part >> 1) ? SM_B : SM_A) + (part & 1) * ATS + r * KPB;
#pragma unroll
        for (int kc = 0; kc < 8; kc++) {
            const int o = kc * 32;
            cpasync16(dst + o, srow + o);
            cpasync16(dst + o + 16, srow + o + 16);
            CP_COMMIT();
        }
    }
    if (tid < 128) {
        ((int*)(smem + SM_YIS))[tid] = g_y[ib + tid];
        ((int*)(smem + SM_YJS))[tid] = g_y[jb + tid];
    }

    // warp/thread geometry: 4 row-groups x 4 col-groups of 32x32 warp tiles
    const int wr = (w & 3) * 32;        // warp row base
    const int wc = (w >> 2) * 32;       // warp col base
    const int g = l >> 3, lr = l & 7;   // ldmatrix lane decode
    const int q = l >> 2;               // quad row (0..7)
    const int e2 = (l & 3) * 2;         // col pair base

    const uint32_t aoff = (uint32_t)((g & 1) * 8 + lr) * KPB + (uint32_t)(g >> 1) * 16;
    const uint32_t boff = (uint32_t)((g >> 1) * 8 + lr) * KPB + (uint32_t)(g & 1) * 16;
    const uint32_t aHi = sb + SM_A;
    const uint32_t aLo = sb + SM_A + ATS;
    const uint32_t bHi = sb + SM_B;
    const uint32_t bLo = sb + SM_B + ATS;

    float acc[2][4][4];
#pragma unroll
    for (int mi = 0; mi < 2; mi++)
#pragma unroll
        for (int ni = 0; ni < 4; ni++)
#pragma unroll
            for (int d = 0; d < 4; d++) acc[mi][ni][d] = 0.f;

#pragma unroll
    for (int kc = 0; kc < 8; kc++) {
        cp_wait(7 - kc);
        __syncthreads();
        const uint32_t ka = (uint32_t)kc * 32;
        uint32_t ah[2][4], al[2][4], bh[4][2], bl[4][2];
#pragma unroll
        for (int mi = 0; mi < 2; mi++) {
            uint32_t o = (uint32_t)(wr + mi * 16) * KPB + aoff + ka;
            ldsm4(ah[mi][0], ah[mi][1], ah[mi][2], ah[mi][3], aHi + o);
            ldsm4(al[mi][0], al[mi][1], al[mi][2], al[mi][3], aLo + o);
        }
#pragma unroll
        for (int nq = 0; nq < 2; nq++) {
            uint32_t o = (uint32_t)(wc + nq * 16) * KPB + boff + ka;
            ldsm4(bh[nq * 2][0], bh[nq * 2][1], bh[nq * 2 + 1][0], bh[nq * 2 + 1][1], bHi + o);
            ldsm4(bl[nq * 2][0], bl[nq * 2][1], bl[nq * 2 + 1][0], bl[nq * 2 + 1][1], bLo + o);
        }
#pragma unroll
        for (int mi = 0; mi < 2; mi++)
#pragma unroll
            for (int ni = 0; ni < 4; ni++) {
                mma16816(acc[mi][ni], ah[mi], bh[ni]);
                mma16816(acc[mi][ni], ah[mi], bl[ni]);
                mma16816(acc[mi][ni], al[mi], bh[ni]);
            }
    }

    // ---- epilogue (a): direct store of S(it,jt) + row-side mining ----
    int rowg[4], yrow[4];
    float mp[4], mn[4];
#pragma unroll
    for (int k4 = 0; k4 < 4; k4++) {
        const int rowi = wr + (k4 >> 1) * 16 + (k4 & 1) * 8 + q;
        rowg[k4] = ib + rowi;
        yrow[k4] = ((const int*)(smem + SM_YIS))[rowi];
        mp[k4] = __int_as_float(0x7f800000);
        mn[k4] = __int_as_float(0xff800000);
    }
    const int* yjs = (const int*)(smem + SM_YJS);
#pragma unroll
    for (int mi = 0; mi < 2; mi++)
#pragma unroll
        for (int h = 0; h < 2; h++) {
            const int ridx = mi * 2 + h;
            float* srow = g_S + (size_t)rowg[ridx] * NB + jb;
#pragma unroll
            for (int ni = 0; ni < 4; ni++) {
                const float s0 = acc[mi][ni][h * 2 + 0];
                const float s1 = acc[mi][ni][h * 2 + 1];
                const int col = wc + ni * 8 + e2;
                stg_cs_f2(srow + col, s0, s1);
#pragma unroll
                for (int e = 0; e < 2; e++) {
                    const float s = e ? s1 : s0;
                    const int jj = jb + col + e;
                    const int yj = yjs[col + e];
                    if (yj == yrow[ridx]) {
                        if (jj != rowg[ridx]) mp[ridx] = fminf(mp[ridx], s);
                    } else {
                        mn[ridx] = fmaxf(mn[ridx], s);
                    }
                }
            }
        }
#pragma unroll
    for (int k4 = 0; k4 < 4; k4++) {
        float a = mp[k4], bv = mn[k4];
        a = fminf(a, __shfl_xor_sync(0xffffffffu, a, 1));
        a = fminf(a, __shfl_xor_sync(0xffffffffu, a, 2));
        bv = fmaxf(bv, __shfl_xor_sync(0xffffffffu, bv, 1));
        bv = fmaxf(bv, __shfl_xor_sync(0xffffffffu, bv, 2));
        if ((l & 3) == 0) {
            atomicMin(&g_minpos[rowg[k4]], fenc(a));
            atomicMax(&g_maxneg[rowg[k4]], fenc(bv));
        }
    }

    // ---- epilogue (b): mirror block + column-side mining (off-diagonal) ----
    if (it != jt) {
        // in-register column partials over this thread's 4 rows, 8 cols
        float pmin[8], pmax[8];
#pragma unroll
        for (int c = 0; c < 8; c++) {
            pmin[c] = __int_as_float(0x7f800000);
            pmax[c] = __int_as_float(0xff800000);
        }
#pragma unroll
        for (int mi = 0; mi < 2; mi++)
#pragma unroll
            for (int h = 0; h < 2; h++) {
                const int ridx = mi * 2 + h;
#pragma unroll
                for (int ni = 0; ni < 4; ni++)
#pragma unroll
                    for (int e = 0; e < 2; e++) {
                        const float s = acc[mi][ni][h * 2 + e];
                        const int c = ni * 2 + e;
                        const int yj = yjs[wc + ni * 8 + e2 + e];
                        if (yj == yrow[ridx]) pmin[c] = fminf(pmin[c], s);
                        else pmax[c] = fmaxf(pmax[c], s);
                    }
            }

        __syncthreads();  // all warps done reading A/B smem
        float* tmin = (float*)(smem + SM_A);
        float* tmax = tmin + 128 * CTS;
        float* stg = (float*)(smem + SM_B);
        // column partial tables: entry = col*CTS + (w&3)*8 + q, one writer each
        const int slot = (w & 3) * 8 + q;
#pragma unroll
        for (int ni = 0; ni < 4; ni++)
#pragma unroll
            for (int e = 0; e < 2; e++) {
                const int col = wc + ni * 8 + e2 + e;
                tmin[col * CTS + slot] = pmin[ni * 2 + e];
                tmax[col * CTS + slot] = pmax[ni * 2 + e];
            }
        // transpose staging for the mirror store
#pragma unroll
        for (int mi = 0; mi < 2; mi++)
#pragma unroll
            for (int h = 0; h < 2; h++) {
                const int row = wr + mi * 16 + h * 8 + q;
#pragma unroll
                for (int ni = 0; ni < 4; ni++) {
                    const int col = wc + ni * 8 + e2;
                    stg[col * TPIT + row] = acc[mi][ni][h * 2 + 0];
                    stg[(col + 1) * TPIT + row] = acc[mi][ni][h * 2 + 1];
                }
            }
        __syncthreads();

        // column reduce + global atomics (threads 0..127, one col each)
        if (tid < 128) {
            const int col = tid;
            float cmp = __int_as_float(0x7f800000);
            float cmx = __int_as_float(0xff800000);
#pragma unroll
            for (int kk = 0; kk < 8; kk++) {
                float4 v = *(const float4*)&tmin[col * CTS + kk * 4];
                cmp = fminf(fminf(cmp, fminf(v.x, v.y)), fminf(v.z, v.w));
                float4 u = *(const float4*)&tmax[col * CTS + kk * 4];
                cmx = fmaxf(fmaxf(cmx, fmaxf(u.x, u.y)), fmaxf(u.z, u.w));
            }
            atomicMin(&g_minpos[jb + col], fenc(cmp));
            atomicMax(&g_maxneg[jb + col], fenc(cmx));
        }

        // mirror store (coalesced)
#pragma unroll
        for (int iter = 0; iter < 8; iter++) {
            const int jr = iter * 16 + w;  // staged row = original col
            float4 v = *(const float4*)&stg[jr * TPIT + l * 4];
            stg_cs_f4(g_S + (size_t)(jb + jr) * NB + ib + l * 4, v);
        }
    }
}

// ============================================================================
// Pass 2: per-row mining + exp sums (streams stored S). Deterministic.
// ============================================================================
__global__ void __launch_bounds__(256) pass2_kernel() {
    const int i = blockIdx.x;
    const float minp = fdec(g_minpos[i]);
    const float maxn = fdec(g_maxneg[i]);
    const int yi = g_y[i];

    float psum = 0.f, nsum = 0.f;
    int flags = 0;

    const float4* Srow = (const float4*)(g_S + (size_t)i * NB);
    const int4* y4 = (const int4*)g_y;

    const int c0 = (threadIdx.x + ((blockIdx.x & 7) << 8)) & 2047;
    for (int t = 0; t < 8; t++) {
        const int c = (c0 + t * 256) & 2047;
        float4 s4 = __ldcs(Srow + c);   // streaming read: read-once data
        int4 yv = y4[c];
        float sv[4] = {s4.x, s4.y, s4.z, s4.w};
        int yy[4] = {yv.x, yv.y, yv.z, yv.w};
        const int j0 = c * 4;
#pragma unroll
        for (int e = 0; e < 4; e++) {
            float s = sv[e];
            int j = j0 + e;
            if (yy[e] != yi) {
                if (s + 0.1f > minp) {
                    flags |= 2;
                    nsum += __expf(50.0f * (s - 1.0f));
                }
            } else if (j != i) {
                if (s - 0.1f < maxn) {
                    flags |= 1;
                    psum += __expf(-2.0f * (s - 1.0f));
                }
            }
        }
    }

    __shared__ float sp[256];
    __shared__ float sn[256];
    __shared__ int fl[256];
    sp[threadIdx.x] = psum;
    sn[threadIdx.x] = nsum;
    fl[threadIdx.x] = flags;
    __syncthreads();
    for (int s = 128; s; s >>= 1) {
        if (threadIdx.x < s) {
            sp[threadIdx.x] += sp[threadIdx.x + s];
            sn[threadIdx.x] += sn[threadIdx.x + s];
            fl[threadIdx.x] |= fl[threadIdx.x + s];
        }
        __syncthreads();
    }
    if (threadIdx.x == 0) {
        int valid = (fl[0] == 3) ? 1 : 0;
        g_row[i] = valid ? (0.5f * log1pf(sp[0]) + 0.02f * log1pf(sn[0])) : 0.f;
        g_valid[i] = valid;
    }
}

__global__ void __launch_bounds__(256) finalize_kernel(float* __restrict__ out) {
    __shared__ float ssum[256];
    __shared__ int scnt[256];
    float s = 0.f;
    int c = 0;
    for (int i = threadIdx.x; i < NB; i += 256) {
        s += g_row[i];
        c += g_valid[i];
    }
    ssum[threadIdx.x] = s;
    scnt[threadIdx.x] = c;
    __syncthreads();
    for (int k = 128; k; k >>= 1) {
        if (threadIdx.x < k) {
            ssum[threadIdx.x] += ssum[threadIdx.x + k];
            scnt[threadIdx.x] += scnt[threadIdx.x + k];
        }
        __syncthreads();
    }
    if (threadIdx.x == 0) {
        int n = scnt[0];
        out[0] = (n > 0) ? (ssum[0] / (float)n) : 0.f;
    }
}

extern "C" void kernel_launch(void* const* d_in, const int* in_sizes, int n_in,
                              void* d_out, int out_size) {
    const float* x = (const float*)d_in[0];
    const void* y = d_in[1];

    cudaFuncSetAttribute(pass1_kernel, cudaFuncAttributeMaxDynamicSharedMemorySize, SMEM_TOTAL);

    detect_kernel<<<1, 256>>>((const unsigned*)y);
    prep_x_kernel<<<NB * ND / 256, 256>>>(x);
    init_y_kernel<<<NB / 256, 256>>>(y);

    pass1_kernel<<<NTRI, 512, SMEM_TOTAL>>>();

    pass2_kernel<<<NB, 256>>>();
    finalize_kernel<<<1, 256>>>((float*)d_out);
}